// round 14
// baseline (speedup 1.0000x reference)
#include <cuda_runtime.h>

// ---------------------------------------------------------------------------
// YOLOv3 loss — 2 launches, warp-local scatter (NO global winner/bitmask).
//   K1: blocks [0,nScatter): one warp per (scale,batch); lane n = target n.
//       Dedup/winner/ignore resolved via warp shuffles; emits fully-resolved
//       32B entries to g_ent (one atomicAdd reservation per warp per anchor).
//       blocks [nScatter,..): dense noobj (overlaps scatter).
//   K2: warp-per-entry eager gather (entry load -> all pred loads issue),
//       last-block finalize.
// Persistent scratch: g_cnt/g_done (reset by K2's elected last block),
// g_ent/g_part (overwritten before use). Nothing large to restore.
// Assumes N <= 32 (dataset: N=20) and B <= 64 (packing).
// ---------------------------------------------------------------------------

#define NCLS 80
#define MAXB 32
#define MAX_ENT  (3 * 3 * MAXB * 32)                     // 5760
#define MAX_PART 2048
#define TPB      256
#define FULL     0xffffffffu

__device__ int    g_cnt;
__device__ int    g_done;
__device__ int4   g_ent[2 * MAX_ENT];                    // 32B resolved entries
__device__ double g_part[2 * MAX_PART];                  // per-block [loss,npos]

__device__ __forceinline__ float sp(float x) {           // fast softplus
    return fmaxf(x, 0.f) + __logf(1.f + __expf(-fabsf(x)));
}
__device__ __forceinline__ float bcef(float x, float t) { return sp(x) - x * t; }
__device__ __forceinline__ float warp_sum(float v) {
    #pragma unroll
    for (int o = 16; o; o >>= 1) v += __shfl_xor_sync(FULL, v, o);
    return v;
}

// ===========================================================================
// K1: warp-local scatter (blocks < nScatter) fused with dense noobj.
// ===========================================================================
__global__ void __launch_bounds__(TPB)
k_scatter_dense(const float* __restrict__ p0,
                const float* __restrict__ p1,
                const float* __restrict__ p2,
                const float* __restrict__ targets,
                const unsigned char* __restrict__ gv,
                const float* __restrict__ anchors,
                int B, int N, int nScatter) {
    int tid = threadIdx.x, lane = tid & 31, w = tid >> 5;
    int blk = blockIdx.x;
    float fsum = 0.f;

    if (blk < nScatter) {
        // ---------------- scatter role: warp per (s,b) ----------------
        __shared__ int flags[2];
        if (tid < 2) flags[tid] = 0;
        __syncthreads();
        for (int p = tid; p < B * N; p += TPB) {
            unsigned char v = gv[p];
            if (v == 0x3F) atomicOr(&flags[0], 1);
            if ((p & 3) != 0 && v != 0) atomicOr(&flags[1], 1);
        }
        __syncthreads();
        int mode = flags[0] ? 0 : (flags[1] ? 2 : 1);    // 0=f32 1=i32 2=u8

        int wg = blk * (TPB / 32) + w;                   // 0 .. 3*B-1
        if (wg < 3 * B) {
            int s = wg / B, b = wg % B;
            int H  = (s == 0) ? 13 : (s == 1) ? 26 : 52;

            // lane n = target n of batch b (N <= 32)
            bool valid = false;
            float gx = 0.f, gy = 0.f, gw = 1.f, gh = 1.f, gc = 0.f;
            if (lane < N) {
                int tidx = b * N + lane;
                if (mode == 0)      valid = ((const float*)gv)[tidx] != 0.f;
                else if (mode == 1) valid = ((const int*)gv)[tidx]   != 0;
                else                valid = gv[tidx] != 0;
                const float* tg = targets + (size_t)tidx * 5;
                gx = tg[0]; gy = tg[1]; gw = tg[2]; gh = tg[3]; gc = tg[4];
            }

            float iou[3];
            int best = 0;
            {
                float best_iou = -1.f;
                #pragma unroll
                for (int a = 0; a < 3; a++) {
                    int ai = (2 - s) * 3 + a;            // ANCHOR_MASKS
                    float aw = anchors[ai * 2 + 0] * (1.f / 416.f);
                    float ah = anchors[ai * 2 + 1] * (1.f / 416.f);
                    float inter = fminf(gw, aw) * fminf(gh, ah);
                    float uni   = gw * gh + aw * ah - inter + 1e-16f;
                    iou[a] = inter / uni;
                    if (iou[a] > best_iou) { best_iou = iou[a]; best = a; }
                }
            }
            int gi = min((int)(gx * H), H - 1);
            int gj = min((int)(gy * H), H - 1);
            int cc = valid ? (gj * 64 + gi) : -1;        // cell code (-1 invalid)

            #pragma unroll
            for (int a = 0; a < 3; a++) {
                bool claim = valid && (best == a || iou[a] > 0.5f);
                // owner = min claiming lane with my cell; winner = max lane
                // with best==a and my cell (all warp-local via shuffles)
                int owner = -1, winner = -1;
                #pragma unroll 8
                for (int l = 0; l < 32; l++) {
                    int  cl = __shfl_sync(FULL, cc, l);
                    int  clm = __shfl_sync(FULL, (int)claim, l);
                    int  bl = __shfl_sync(FULL, best, l);
                    if (cc >= 0 && cl == cc) {
                        if (clm && owner < 0) owner = l;
                        if (bl == a && cl >= 0) winner = l;  // ascending -> max
                    }
                }
                bool emit = claim && (owner == lane);
                unsigned int mv = __ballot_sync(FULL, emit);
                int total = __popc(mv);
                int base = 0;
                if (total > 0) {
                    if (lane == 0) base = atomicAdd(&g_cnt, total);
                    base = __shfl_sync(FULL, base, 0);
                }
                // winner target data (unconditional shuffles)
                int wsrc = (winner >= 0) ? winner : 0;
                float wgx = __shfl_sync(FULL, gx, wsrc);
                float wgy = __shfl_sync(FULL, gy, wsrc);
                float wgw = __shfl_sync(FULL, gw, wsrc);
                float wgh = __shfl_sync(FULL, gh, wsrc);
                float wgc = __shfl_sync(FULL, gc, wsrc);
                if (emit) {
                    int rank = __popc(mv & ((1u << lane) - 1));
                    int slot = base + rank;
                    int pk = (s << 20) | (b << 14) | (a << 12) | (gj << 6) | gi;
                    int wn = winner + 1;                 // 0 if winner==-1
                    int gcls = 0;
                    float tx = 0.f, ty = 0.f, tw2 = 0.f, th2 = 0.f;
                    if (wn > 0) {
                        int ai = (2 - s) * 3 + a;
                        float aw = anchors[ai * 2 + 0] * (1.f / 416.f);
                        float ah = anchors[ai * 2 + 1] * (1.f / 416.f);
                        gcls = (int)wgc;
                        tx = wgx * H - gi;  ty = wgy * H - gj;
                        tw2 = logf(wgw / aw); th2 = logf(wgh / ah);
                    }
                    if (slot < MAX_ENT) {
                        g_ent[2 * slot] = make_int4(pk, wn, gcls,
                                                    __float_as_int(tx));
                        g_ent[2 * slot + 1] = make_int4(__float_as_int(ty),
                                                        __float_as_int(tw2),
                                                        __float_as_int(th2), 0);
                    }
                }
            }
        }
    } else {
        // ---------------- dense noobj role ----------------
        int t  = (blk - nScatter) * TPB + tid;
        int q1 = B * 3 * 169;          // scale-1 quads (== scale-0 elements)
        int Q  = B * 3 * 845;
        if (t < Q) {
            float sum;
            if (t < q1) {
                int r = t / 169, qi = t - r * 169;
                size_t row = (size_t)((r / 3) * 255 + (r % 3) * 85 + 4);
                float4 v = *(const float4*)(p1 + row * 676 + qi * 4);
                sum = sp(v.x) + sp(v.y) + sp(v.z) + sp(v.w);
                sum += sp(p0[row * 169 + qi]);
            } else {
                int u = t - q1;
                int r = u / 676, qi = u - r * 676;
                size_t row = (size_t)((r / 3) * 255 + (r % 3) * 85 + 4);
                float4 v = *(const float4*)(p2 + row * 2704 + qi * 4);
                sum = sp(v.x) + sp(v.y) + sp(v.z) + sp(v.w);
            }
            fsum = 0.5f * sum;
        }
    }

    // block reduction -> plain store (scatter blocks store zeros)
    __shared__ float ws[TPB / 32];
    fsum = warp_sum(fsum);
    if (lane == 0) ws[w] = fsum;
    __syncthreads();
    if (tid == 0) {
        float Lf = 0.f;
        #pragma unroll
        for (int k = 0; k < TPB / 32; k++) Lf += ws[k];
        g_part[2 * blk]     = (double)Lf;
        g_part[2 * blk + 1] = 0.0;
    }
}

// ===========================================================================
// K2: warp-per-entry eager gather + last-block finalize.
// Single dependent hop (entry), then conf/coords/classes all issue at once.
// ===========================================================================
__global__ void __launch_bounds__(TPB)
k_sparse_final(const float* __restrict__ p0,
               const float* __restrict__ p1,
               const float* __restrict__ p2,
               int B, int nPartK1, float* out) {
    int tid = threadIdx.x, lane = tid & 31, w = tid >> 5;
    int blk = blockIdx.x;
    __shared__ double sl[TPB / 32], sn[TPB / 32];
    __shared__ int is_last;

    int cnt = g_cnt;
    if (cnt > MAX_ENT) cnt = MAX_ENT;
    int gw_id = blk * (TPB / 32) + w;
    double contrib = 0.0, np = 0.0;

    if (gw_id < cnt) {
        // hop 1: resolved entry (2x LDG.128 broadcast)
        int4 v0 = g_ent[2 * gw_id];
        int4 v1 = g_ent[2 * gw_id + 1];
        int pk = v0.x, wn = v0.y, gcls = v0.z;
        float tx = __int_as_float(v0.w);
        float ty = __int_as_float(v1.x);
        float tw = __int_as_float(v1.y);
        float th = __int_as_float(v1.z);

        int s = (pk >> 20) & 3, b = (pk >> 14) & 63;
        int a = (pk >> 12) & 3, j = (pk >> 6) & 63, i = pk & 63;
        int H  = (s == 0) ? 13 : (s == 1) ? 26 : 52;
        int HW = H * H;
        const float* pred = (s == 0) ? p0 : (s == 1) ? p1 : p2;
        size_t base = ((size_t)(b * 255 + a * 85)) * HW + (size_t)j * H + i;

        // hop 2: everything issues in parallel
        float conf = pred[base + (size_t)4 * HW];
        float px = 0.f, py = 0.f, pw = 0.f, ph = 0.f;
        if (lane == 0) {
            px = pred[base];
            py = pred[base + (size_t)1 * HW];
            pw = pred[base + (size_t)2 * HW];
            ph = pred[base + (size_t)3 * HW];
        }
        float pc0 = pred[base + (size_t)(5 + lane)      * HW];
        float pc1 = pred[base + (size_t)(5 + lane + 32) * HW];
        float pc2 = (lane < NCLS - 64)
                  ? pred[base + (size_t)(5 + lane + 64) * HW] : 0.f;
        float lcls = sp(pc0) + sp(pc1) + ((lane < NCLS - 64) ? sp(pc2) : 0.f);

        if (wn > 0) {
            if (lane == gcls)           lcls -= pc0;     // bce(x,1)=sp(x)-x
            else if (lane + 32 == gcls) lcls -= pc1;
            else if (lane + 64 == gcls) lcls -= pc2;
            lcls = warp_sum(lcls);
            if (lane == 0) {
                float lcoord = bcef(px, tx) + bcef(py, ty)
                             + (pw - tw) * (pw - tw) + (ph - th) * (ph - th);
                contrib = (double)(5.0f * lcoord + sp(-conf) + lcls)
                        - 0.5 * (double)sp(conf);        // remove dense noobj
                np = 1.0;
            }
        } else if (lane == 0) {
            contrib = -0.5 * (double)sp(conf);           // ignore-only cell
        }
    }

    if (lane == 0) { sl[w] = contrib; sn[w] = np; }
    if (tid == 0) is_last = 0;
    __syncthreads();
    if (tid == 0) {
        double L = 0.0, P = 0.0;
        #pragma unroll
        for (int k = 0; k < TPB / 32; k++) { L += sl[k]; P += sn[k]; }
        g_part[2 * (nPartK1 + blk)]     = L;
        g_part[2 * (nPartK1 + blk) + 1] = P;
        __threadfence();
        int prev = atomicAdd(&g_done, 1);                // captured return:
        if (prev == (int)gridDim.x - 1) is_last = 1;     // unique last block
    }
    __syncthreads();

    if (is_last) {
        int P = nPartK1 + (int)gridDim.x;
        double L = 0.0, Np = 0.0;
        for (int k = tid; k < P; k += TPB) {
            L  += g_part[2 * k];
            Np += g_part[2 * k + 1];
        }
        #pragma unroll
        for (int o = 16; o; o >>= 1) {
            L  += __shfl_xor_sync(FULL, L, o);
            Np += __shfl_xor_sync(FULL, Np, o);
        }
        if (lane == 0) { sl[w] = L; sn[w] = Np; }
        __syncthreads();
        if (tid == 0) {
            double l = 0.0, n = 0.0;
            #pragma unroll
            for (int k = 0; k < TPB / 32; k++) { l += sl[k]; n += sn[k]; }
            out[0] = (float)((n > 0.0) ? l / n : l / (double)B);
            g_cnt = 0; g_done = 0;                       // restore invariants
        }
    }
}

extern "C" void kernel_launch(void* const* d_in, const int* in_sizes, int n_in,
                              void* d_out, int out_size) {
    const float* p0      = (const float*)d_in[0];
    const float* p1      = (const float*)d_in[1];
    const float* p2      = (const float*)d_in[2];
    const float* targets = (const float*)d_in[3];
    const unsigned char* gvalid = (const unsigned char*)d_in[4];
    const float* anchors = (const float*)d_in[5];
    float* out = (float*)d_out;

    int B = in_sizes[0] / (255 * 13 * 13);
    int N = in_sizes[3] / (B * 5);
    if (B > MAXB) B = MAXB;   // scratch bound (shapes fixed at B=32)
    if (N > 32)   N = 32;     // warp-local scatter bound (dataset: N=20)

    int nScatter = (3 * B + (TPB / 32) - 1) / (TPB / 32);   // 12 @ B=32
    int nDense   = (B * 3 * 845 + TPB - 1) / TPB;           // 317 @ B=32
    int gridK1   = nScatter + nDense;                       // 329

    int ent_max = 3 * 3 * B * N;
    if (ent_max > MAX_ENT) ent_max = MAX_ENT;
    int gridK2 = (ent_max + (TPB / 32) - 1) / (TPB / 32);   // 720 @ bound

    if (gridK1 + gridK2 > MAX_PART) gridK2 = MAX_PART - gridK1;

    k_scatter_dense<<<gridK1, TPB>>>(p0, p1, p2, targets, gvalid, anchors,
                                     B, N, nScatter);
    k_sparse_final <<<gridK2, TPB>>>(p0, p1, p2, B, gridK1, out);
}

// round 15
// speedup vs baseline: 1.1674x; 1.1674x over previous
#include <cuda_runtime.h>

// ---------------------------------------------------------------------------
// YOLOv3 loss — SINGLE LAUNCH, block-local scatter+gather.
//   Blocks [0, 3B):  sparse role. Warp 0 resolves (s,b) via warp shuffles
//                    (dedup/winner/ignore, N<=32 targets in lanes) -> smem
//                    entries; then all 8 warps gather/accumulate them.
//   Blocks [3B, ..): dense noobj over all conf channels (float4).
//   Last finished block (captured atomicAdd) reduces g_part, writes out[0],
//   resets g_done. Persistent state: g_done (zero at entry, restored),
//   g_part (overwritten before use). No spins, no cross-block handoff.
// Assumes N <= 32 (dataset N=20), B <= 32.
// ---------------------------------------------------------------------------

#define NCLS 80
#define MAXB 32
#define MAX_PART 1024
#define TPB      256
#define FULL     0xffffffffu

__device__ int    g_done;
__device__ double g_part[2 * MAX_PART];                  // per-block [loss,npos]

__device__ __forceinline__ float sp(float x) {           // fast softplus
    return fmaxf(x, 0.f) + __logf(1.f + __expf(-fabsf(x)));
}
__device__ __forceinline__ float bcef(float x, float t) { return sp(x) - x * t; }
__device__ __forceinline__ float warp_sum(float v) {
    #pragma unroll
    for (int o = 16; o; o >>= 1) v += __shfl_xor_sync(FULL, v, o);
    return v;
}

__global__ void __launch_bounds__(TPB)
k_all(const float* __restrict__ p0,
      const float* __restrict__ p1,
      const float* __restrict__ p2,
      const float* __restrict__ targets,
      const unsigned char* __restrict__ gv,
      const float* __restrict__ anchors,
      int B, int N, int nSparse, float* out) {
    int tid = threadIdx.x, lane = tid & 31, w = tid >> 5;
    int blk = blockIdx.x;

    __shared__ double sl[TPB / 32], sn[TPB / 32];
    __shared__ int is_last;

    float  fsum = 0.f;            // dense partial
    double dsum = 0.0, psum = 0.0;  // sparse partials (lane 0 of each warp)

    if (blk < nSparse) {
        // ================== SPARSE ROLE: block owns (s,b) ==================
        __shared__ int4 sent[2 * 96];                    // <= 3N entries, 32B
        __shared__ int  scnt, flags[2];
        if (tid < 2) flags[tid] = 0;
        if (tid == 0) scnt = 0;
        __syncthreads();
        // classify gt_valid dtype (640B scan, L2-resident)
        for (int p = tid; p < B * N; p += TPB) {
            unsigned char v = gv[p];
            if (v == 0x3F) atomicOr(&flags[0], 1);
            if ((p & 3) != 0 && v != 0) atomicOr(&flags[1], 1);
        }
        __syncthreads();
        int mode = flags[0] ? 0 : (flags[1] ? 2 : 1);    // 0=f32 1=i32 2=u8

        int s = blk / B, b = blk % B;
        int H = (s == 0) ? 13 : (s == 1) ? 26 : 52;

        if (w == 0) {
            // ---- warp-local scatter: lane n = target n (R14-proven) ----
            bool valid = false;
            float gx = 0.f, gy = 0.f, gw = 1.f, gh = 1.f, gc = 0.f;
            if (lane < N) {
                int tidx = b * N + lane;
                if (mode == 0)      valid = ((const float*)gv)[tidx] != 0.f;
                else if (mode == 1) valid = ((const int*)gv)[tidx]   != 0;
                else                valid = gv[tidx] != 0;
                const float* tg = targets + (size_t)tidx * 5;
                gx = tg[0]; gy = tg[1]; gw = tg[2]; gh = tg[3]; gc = tg[4];
            }

            float iou[3];
            int best = 0;
            {
                float best_iou = -1.f;
                #pragma unroll
                for (int a = 0; a < 3; a++) {
                    int ai = (2 - s) * 3 + a;            // ANCHOR_MASKS
                    float aw = anchors[ai * 2 + 0] * (1.f / 416.f);
                    float ah = anchors[ai * 2 + 1] * (1.f / 416.f);
                    float inter = fminf(gw, aw) * fminf(gh, ah);
                    float uni   = gw * gh + aw * ah - inter + 1e-16f;
                    iou[a] = inter / uni;
                    if (iou[a] > best_iou) { best_iou = iou[a]; best = a; }
                }
            }
            int gi = min((int)(gx * H), H - 1);
            int gj = min((int)(gy * H), H - 1);
            int cc = valid ? (gj * 64 + gi) : -1;        // cell code

            #pragma unroll
            for (int a = 0; a < 3; a++) {
                bool claim = valid && (best == a || iou[a] > 0.5f);
                int owner = -1, winner = -1;
                #pragma unroll 8
                for (int l = 0; l < 32; l++) {
                    int cl  = __shfl_sync(FULL, cc, l);
                    int clm = __shfl_sync(FULL, (int)claim, l);
                    int bl  = __shfl_sync(FULL, best, l);
                    if (cc >= 0 && cl == cc) {
                        if (clm && owner < 0) owner = l;
                        if (bl == a) winner = l;         // ascending -> max n
                    }
                }
                bool emit = claim && (owner == lane);
                unsigned int mv = __ballot_sync(FULL, emit);
                int base = 0;
                if (__popc(mv) > 0) {
                    if (lane == 0) base = atomicAdd(&scnt, __popc(mv));
                    base = __shfl_sync(FULL, base, 0);
                }
                int wsrc = (winner >= 0) ? winner : 0;
                float wgx = __shfl_sync(FULL, gx, wsrc);
                float wgy = __shfl_sync(FULL, gy, wsrc);
                float wgw = __shfl_sync(FULL, gw, wsrc);
                float wgh = __shfl_sync(FULL, gh, wsrc);
                float wgc = __shfl_sync(FULL, gc, wsrc);
                if (emit) {
                    int slot = base + __popc(mv & ((1u << lane) - 1));
                    int pk = (a << 12) | (gj << 6) | gi;
                    int wn = winner + 1;
                    int gcls = 0;
                    float tx = 0.f, ty = 0.f, tw2 = 0.f, th2 = 0.f;
                    if (wn > 0) {
                        int ai = (2 - s) * 3 + a;
                        float aw = anchors[ai * 2 + 0] * (1.f / 416.f);
                        float ah = anchors[ai * 2 + 1] * (1.f / 416.f);
                        gcls = (int)wgc;
                        tx = wgx * H - gi;  ty = wgy * H - gj;
                        tw2 = logf(wgw / aw); th2 = logf(wgh / ah);
                    }
                    sent[2 * slot] = make_int4(pk, wn, gcls,
                                               __float_as_int(tx));
                    sent[2 * slot + 1] = make_int4(__float_as_int(ty),
                                                   __float_as_int(tw2),
                                                   __float_as_int(th2), 0);
                }
            }
        }
        __syncthreads();

        // ---- all 8 warps consume the block's entries (eager gather) ----
        int cnt = scnt;
        int HW = H * H;
        const float* pred = (s == 0) ? p0 : (s == 1) ? p1 : p2;
        for (int e = w; e < cnt; e += TPB / 32) {
            int4 v0 = sent[2 * e];
            int4 v1 = sent[2 * e + 1];
            int pk = v0.x, wn = v0.y, gcls = v0.z;
            float tx = __int_as_float(v0.w);
            float ty = __int_as_float(v1.x);
            float tw = __int_as_float(v1.y);
            float th = __int_as_float(v1.z);
            int a = (pk >> 12) & 3, j = (pk >> 6) & 63, i = pk & 63;
            size_t base = ((size_t)(b * 255 + a * 85)) * HW
                        + (size_t)j * H + i;

            // eager issue: conf/coords/classes all in parallel
            float conf = pred[base + (size_t)4 * HW];
            float px = 0.f, py = 0.f, pw = 0.f, ph = 0.f;
            if (lane == 0) {
                px = pred[base];
                py = pred[base + (size_t)1 * HW];
                pw = pred[base + (size_t)2 * HW];
                ph = pred[base + (size_t)3 * HW];
            }
            float pc0 = pred[base + (size_t)(5 + lane)      * HW];
            float pc1 = pred[base + (size_t)(5 + lane + 32) * HW];
            float pc2 = (lane < NCLS - 64)
                      ? pred[base + (size_t)(5 + lane + 64) * HW] : 0.f;
            float lcls = sp(pc0) + sp(pc1)
                       + ((lane < NCLS - 64) ? sp(pc2) : 0.f);

            if (wn > 0) {
                if (lane == gcls)           lcls -= pc0;   // bce(x,1)=sp(x)-x
                else if (lane + 32 == gcls) lcls -= pc1;
                else if (lane + 64 == gcls) lcls -= pc2;
                lcls = warp_sum(lcls);
                if (lane == 0) {
                    float lcoord = bcef(px, tx) + bcef(py, ty)
                                 + (pw - tw) * (pw - tw)
                                 + (ph - th) * (ph - th);
                    dsum += (double)(5.0f * lcoord + sp(-conf) + lcls)
                          - 0.5 * (double)sp(conf);       // remove dense term
                    psum += 1.0;
                }
            } else if (lane == 0) {
                dsum -= 0.5 * (double)sp(conf);           // ignore-only cell
            }
        }
    } else {
        // ================== DENSE NOOBJ ROLE ==================
        int t  = (blk - nSparse) * TPB + tid;
        int q1 = B * 3 * 169;          // scale-1 quads (== scale-0 elements)
        int Q  = B * 3 * 845;
        if (t < Q) {
            float sum;
            if (t < q1) {
                int r = t / 169, qi = t - r * 169;
                size_t row = (size_t)((r / 3) * 255 + (r % 3) * 85 + 4);
                float4 v = *(const float4*)(p1 + row * 676 + qi * 4);
                sum = sp(v.x) + sp(v.y) + sp(v.z) + sp(v.w);
                sum += sp(p0[row * 169 + qi]);
            } else {
                int u = t - q1;
                int r = u / 676, qi = u - r * 676;
                size_t row = (size_t)((r / 3) * 255 + (r % 3) * 85 + 4);
                float4 v = *(const float4*)(p2 + row * 2704 + qi * 4);
                sum = sp(v.x) + sp(v.y) + sp(v.z) + sp(v.w);
            }
            fsum = 0.5f * sum;
        }
    }

    // ================== BLOCK REDUCTION ==================
    double dl = dsum + (double)warp_sum(fsum) * ((lane == 0) ? 1.0 : 0.0);
    // (warp_sum leaves full warp total in every lane; count it once)
    if (lane == 0) { sl[w] = dl; sn[w] = psum; }
    if (tid == 0) is_last = 0;
    __syncthreads();
    if (tid == 0) {
        double L = 0.0, P = 0.0;
        #pragma unroll
        for (int k = 0; k < TPB / 32; k++) { L += sl[k]; P += sn[k]; }
        g_part[2 * blk]     = L;
        g_part[2 * blk + 1] = P;
        __threadfence();
        int prev = atomicAdd(&g_done, 1);                // captured return:
        if (prev == (int)gridDim.x - 1) is_last = 1;     // unique last block
    }
    __syncthreads();

    // ================== LAST BLOCK: FINALIZE ==================
    if (is_last) {
        int P = (int)gridDim.x;
        double L = 0.0, Np = 0.0;
        for (int k = tid; k < P; k += TPB) {
            L  += g_part[2 * k];
            Np += g_part[2 * k + 1];
        }
        #pragma unroll
        for (int o = 16; o; o >>= 1) {
            L  += __shfl_xor_sync(FULL, L, o);
            Np += __shfl_xor_sync(FULL, Np, o);
        }
        if (lane == 0) { sl[w] = L; sn[w] = Np; }
        __syncthreads();
        if (tid == 0) {
            double l = 0.0, n = 0.0;
            #pragma unroll
            for (int k = 0; k < TPB / 32; k++) { l += sl[k]; n += sn[k]; }
            out[0] = (float)((n > 0.0) ? l / n : l / (double)B);
            g_done = 0;                                  // restore invariant
        }
    }
}

extern "C" void kernel_launch(void* const* d_in, const int* in_sizes, int n_in,
                              void* d_out, int out_size) {
    const float* p0      = (const float*)d_in[0];
    const float* p1      = (const float*)d_in[1];
    const float* p2      = (const float*)d_in[2];
    const float* targets = (const float*)d_in[3];
    const unsigned char* gvalid = (const unsigned char*)d_in[4];
    const float* anchors = (const float*)d_in[5];
    float* out = (float*)d_out;

    int B = in_sizes[0] / (255 * 13 * 13);
    int N = in_sizes[3] / (B * 5);
    if (B > MAXB) B = MAXB;   // scratch bound (shapes fixed at B=32)
    if (N > 32)   N = 32;     // warp-local scatter bound (dataset: N=20)

    int nSparse = 3 * B;                                 // 96 @ B=32
    int nDense  = (B * 3 * 845 + TPB - 1) / TPB;         // 317 @ B=32
    int grid    = nSparse + nDense;                      // 413 <= MAX_PART

    k_all<<<grid, TPB>>>(p0, p1, p2, targets, gvalid, anchors,
                         B, N, nSparse, out);
}